// round 2
// baseline (speedup 1.0000x reference)
#include <cuda_runtime.h>
#include <cstdint>

// ---------------------------------------------------------------------------
// GAT hierarchical 2-layer, fully restructured.
// Layer0 (both levels): aggregate RAW features with attention computed from
//   precomputed projection vectors P0 = W0_h @ a0.
// Layer1: logits computed directly on y1/y0 via Q = contract(W0, P1),
//   aggregation commutes with W0 => W0 applied AFTER aggregation on only
//   1024x4 rows. Removes the 10240-row GEMM entirely.
// Chain:  y1 = attn(h1,h2,P0)      [10240,4,128]
//         y0 = attn(h0,h1,P0)      [1024,4,128]
//         u  = attn(y0,y1,Q)       [1024,4(h'),512]   (aggregates y1 rows)
//         v  = u @ W0 (per-h blk)  [1024,4(h'),512]
//         hs0= v @ W1 (per-h' blk) [1024,512]
//         out= hs0 @ Wfc           [1024,256]
// ---------------------------------------------------------------------------

// scratch layout (floats)
static constexpr size_t OFF_Y1 = 0;                        // [10240,512]
static constexpr size_t OFF_Y0 = OFF_Y1 + 10240ull * 512;  // [1024,512]
static constexpr size_t OFF_U  = OFF_Y0 + 1024ull * 512;   // [1024,2048]
static constexpr size_t OFF_V  = OFF_U  + 1024ull * 2048;  // [1024,2048]
static constexpr size_t OFF_H  = OFF_V  + 1024ull * 2048;  // [1024,512]
static constexpr size_t OFF_P0 = OFF_H  + 1024ull * 512;   // P0s[512],P0n[512]
static constexpr size_t OFF_P1 = OFF_P0 + 1024;            // P1s[2048],P1n[2048]
static constexpr size_t OFF_Q  = OFF_P1 + 4096;            // Qs[2048],Qn[2048]
static constexpr size_t SCRATCH_FLOATS = OFF_Q + 4096;

__device__ float g_scratch[SCRATCH_FLOATS];

// ---------------------------------------------------------------------------
// P0[h*128+f] = sum_d W0[f, h*128+d] * a0[h,d]   (512 threads)
// ---------------------------------------------------------------------------
__global__ void prep0_kernel(const float* __restrict__ W0,
                             const float* __restrict__ a0s,
                             const float* __restrict__ a0n,
                             float* __restrict__ P0)
{
    int t = blockIdx.x * blockDim.x + threadIdx.x;
    if (t >= 512) return;
    int h = t >> 7, f = t & 127;
    const float* wrow = W0 + (size_t)f * 512 + h * 128;
    const float* as = a0s + h * 128;
    const float* an = a0n + h * 128;
    float s = 0.f, n = 0.f;
    #pragma unroll 4
    for (int d = 0; d < 128; d++) {
        float wv = wrow[d];
        s = fmaf(wv, as[d], s);
        n = fmaf(wv, an[d], n);
    }
    P0[t] = s;
    P0[512 + t] = n;
}

// ---------------------------------------------------------------------------
// P1[h'*512+f] = sum_d W1[f, h'*128+d] * a1[h',d]   (2048 threads)
// ---------------------------------------------------------------------------
__global__ void prep1_kernel(const float* __restrict__ W1,
                             const float* __restrict__ a1s,
                             const float* __restrict__ a1n,
                             float* __restrict__ P1)
{
    int t = blockIdx.x * blockDim.x + threadIdx.x;
    if (t >= 2048) return;
    int hp = t >> 9, f = t & 511;
    const float* wrow = W1 + (size_t)f * 512 + hp * 128;
    const float* as = a1s + hp * 128;
    const float* an = a1n + hp * 128;
    float s = 0.f, n = 0.f;
    #pragma unroll 4
    for (int d = 0; d < 128; d++) {
        float wv = wrow[d];
        s = fmaf(wv, as[d], s);
        n = fmaf(wv, an[d], n);
    }
    P1[t] = s;
    P1[2048 + t] = n;
}

// ---------------------------------------------------------------------------
// Q[h'*512 + h*128 + k] = sum_d W0[k, h*128+d] * P1[h'*512 + h*128+d]
// computes Qs (from P1s) and Qn (from P1n).  (2048 threads)
// ---------------------------------------------------------------------------
__global__ void prepQ_kernel(const float* __restrict__ W0,
                             const float* __restrict__ P1,
                             float* __restrict__ Q)
{
    int t = blockIdx.x * blockDim.x + threadIdx.x;
    if (t >= 2048) return;
    int hp = t >> 9, i = t & 511;
    int h = i >> 7, k = i & 127;
    const float* wrow = W0 + (size_t)k * 512 + h * 128;
    const float* ps = P1 + hp * 512 + h * 128;
    const float* pn = P1 + 2048 + hp * 512 + h * 128;
    float s = 0.f, n = 0.f;
    #pragma unroll 4
    for (int d = 0; d < 128; d++) {
        float wv = wrow[d];
        s = fmaf(wv, ps[d], s);
        n = fmaf(wv, pn[d], n);
    }
    Q[t] = s;
    Q[2048 + t] = n;
}

// ---------------------------------------------------------------------------
// Attention + raw-row aggregation. One block (128 threads) per group.
//   xs: [G,F], xn: [G,E,F], Ws/Wn: [4,F], y: [G,4,F]
// Logits: warp w = head; lane e < E computes full dot(xn[e], Wn[w]);
// lane E computes dot(xs, Ws[w]). Softmax in-register over lanes.
// y[h][f] = sum_e alpha[e,h] * xn[e][f].
// ---------------------------------------------------------------------------
template<int F, int E>
__global__ __launch_bounds__(128)
void attn_kernel(const float* __restrict__ xs,
                 const float* __restrict__ xn,
                 const float* __restrict__ Ws,
                 const float* __restrict__ Wn,
                 float* __restrict__ y)
{
    constexpr int FP = F + 4;         // padded row stride (floats), 16B-aligned
    const int g    = blockIdx.x;
    const int tid  = threadIdx.x;
    const int w    = tid >> 5;        // warp = head
    const int lane = tid & 31;

    __shared__ float sxn[(E + 1) * FP];
    __shared__ float salpha[E * 4];

    // load neighbor rows (vectorized), self row goes to row E
    const float4* gxn = (const float4*)(xn + (size_t)g * E * F);
    constexpr int NV = E * (F / 4);
    for (int i = tid; i < NV; i += 128) {
        int e  = i / (F / 4);
        int k4 = i & (F / 4 - 1);
        *(float4*)&sxn[e * FP + 4 * k4] = gxn[i];
    }
    const float4* gxs = (const float4*)(xs + (size_t)g * F);
    for (int i = tid; i < F / 4; i += 128)
        *(float4*)&sxn[E * FP + 4 * i] = gxs[i];
    __syncthreads();

    // per-lane dot products (lane e<E: neighbor e vs Wn; lane==E: self vs Ws)
    const float* wv  = (lane < E) ? (Wn + w * F) : (Ws + w * F);
    const float* row = &sxn[((lane < E) ? lane : E) * FP];
    float a0 = 0.f, a1 = 0.f, a2 = 0.f, a3 = 0.f;
    #pragma unroll 8
    for (int k = 0; k < F; k += 4) {
        float4 wq = __ldg((const float4*)(wv + k));  // broadcast across lanes
        a0 = fmaf(row[k + 0], wq.x, a0);
        a1 = fmaf(row[k + 1], wq.y, a1);
        a2 = fmaf(row[k + 2], wq.z, a2);
        a3 = fmaf(row[k + 3], wq.w, a3);
    }
    float dot = (a0 + a1) + (a2 + a3);

    float es = __shfl_sync(0xffffffffu, dot, E);
    float l  = es + dot;
    l = (l >= 0.f) ? l : 0.2f * l;                   // leaky_relu(0.2)
    float v = (lane < E) ? l : -3.4e38f;

    // softmax over lanes 0..E-1
    float m = v;
    #pragma unroll
    for (int o = 16; o; o >>= 1) m = fmaxf(m, __shfl_xor_sync(0xffffffffu, m, o));
    float p = (lane < E) ? __expf(v - m) : 0.f;
    float s = p;
    #pragma unroll
    for (int o = 16; o; o >>= 1) s += __shfl_xor_sync(0xffffffffu, s, o);
    if (lane < E) salpha[lane * 4 + w] = p / s;
    __syncthreads();

    // aggregate raw rows: thread tid covers columns {c*128+tid}
    constexpr int C = F / 128;
    float acc[C][4];
    #pragma unroll
    for (int c = 0; c < C; c++)
        #pragma unroll
        for (int h = 0; h < 4; h++) acc[c][h] = 0.f;

    for (int e = 0; e < E; e++) {
        float al[4];
        #pragma unroll
        for (int h = 0; h < 4; h++) al[h] = salpha[e * 4 + h];
        #pragma unroll
        for (int c = 0; c < C; c++) {
            float val = sxn[e * FP + c * 128 + tid];
            #pragma unroll
            for (int h = 0; h < 4; h++) acc[c][h] = fmaf(al[h], val, acc[c][h]);
        }
    }
    float* gy = y + (size_t)g * (4 * F);
    #pragma unroll
    for (int h = 0; h < 4; h++)
        #pragma unroll
        for (int c = 0; c < C; c++)
            gy[h * F + c * 128 + tid] = acc[c][h];
}

// ---------------------------------------------------------------------------
// fp32 tiled GEMM: C = A @ B. 64x64 tile, BK=16, 256 threads, 4x4/thread.
// Batched via blockIdx.z with element offsets.
// ---------------------------------------------------------------------------
__global__ __launch_bounds__(256)
void gemm_kernel(const float* __restrict__ A, const float* __restrict__ B,
                 float* __restrict__ C,
                 int K, int lda, int ldb, int ldc,
                 int offA, int offB, int offC)
{
    A += (size_t)blockIdx.z * offA;
    B += (size_t)blockIdx.z * offB;
    C += (size_t)blockIdx.z * offC;

    const int row0 = blockIdx.y * 64;
    const int col0 = blockIdx.x * 64;
    const int tx = threadIdx.x;       // 0..15
    const int ty = threadIdx.y;       // 0..15
    const int tid = ty * 16 + tx;

    __shared__ float As[16][64];
    __shared__ float Bs[16][64];

    const int ar = tid >> 2;
    const int ac = (tid & 3) * 4;
    const int br = tid >> 4;
    const int bc = (tid & 15) * 4;

    float acc[4][4];
    #pragma unroll
    for (int i = 0; i < 4; i++)
        #pragma unroll
        for (int j = 0; j < 4; j++) acc[i][j] = 0.f;

    for (int k0 = 0; k0 < K; k0 += 16) {
        float4 av = *(const float4*)(A + (size_t)(row0 + ar) * lda + k0 + ac);
        As[ac + 0][ar] = av.x;
        As[ac + 1][ar] = av.y;
        As[ac + 2][ar] = av.z;
        As[ac + 3][ar] = av.w;
        float4 bv = *(const float4*)(B + (size_t)(k0 + br) * ldb + col0 + bc);
        *(float4*)&Bs[br][bc] = bv;
        __syncthreads();

        #pragma unroll
        for (int k = 0; k < 16; k++) {
            float4 a4 = *(const float4*)&As[k][ty * 4];
            float4 b4 = *(const float4*)&Bs[k][tx * 4];
            float a[4] = {a4.x, a4.y, a4.z, a4.w};
            float b[4] = {b4.x, b4.y, b4.z, b4.w};
            #pragma unroll
            for (int i = 0; i < 4; i++)
                #pragma unroll
                for (int j = 0; j < 4; j++)
                    acc[i][j] = fmaf(a[i], b[j], acc[i][j]);
        }
        __syncthreads();
    }

    #pragma unroll
    for (int i = 0; i < 4; i++) {
        float4 o = {acc[i][0], acc[i][1], acc[i][2], acc[i][3]};
        *(float4*)(C + (size_t)(row0 + ty * 4 + i) * ldc + col0 + tx * 4) = o;
    }
}

// ---------------------------------------------------------------------------
extern "C" void kernel_launch(void* const* d_in, const int* in_sizes, int n_in,
                              void* d_out, int out_size)
{
    const float* h0  = (const float*)d_in[0];   // [1024,128]
    const float* h1  = (const float*)d_in[1];   // [1024,10,128]
    const float* h2  = (const float*)d_in[2];   // [1024,250,128]
    const float* W0  = (const float*)d_in[3];   // [128,512]
    const float* a0s = (const float*)d_in[4];
    const float* a0n = (const float*)d_in[5];
    const float* W1  = (const float*)d_in[6];   // [512,512]
    const float* a1s = (const float*)d_in[7];
    const float* a1n = (const float*)d_in[8];
    const float* Wfc = (const float*)d_in[9];   // [512,256]
    float* out = (float*)d_out;                 // [1024,256]

    float* scr = nullptr;
    cudaGetSymbolAddress((void**)&scr, g_scratch);
    float* y1  = scr + OFF_Y1;
    float* y0  = scr + OFF_Y0;
    float* u   = scr + OFF_U;
    float* v   = scr + OFF_V;
    float* hs0 = scr + OFF_H;
    float* P0  = scr + OFF_P0;
    float* P1  = scr + OFF_P1;
    float* Q   = scr + OFF_Q;

    // weight preprocessing
    prep0_kernel<<<2, 256>>>(W0, a0s, a0n, P0);
    prep1_kernel<<<8, 256>>>(W1, a1s, a1n, P1);
    prepQ_kernel<<<8, 256>>>(W0, P1, Q);

    // layer0: aggregate raw features
    attn_kernel<128, 25><<<10240, 128>>>(h1, h2, P0, P0 + 512, y1);
    attn_kernel<128, 10><<<1024, 128>>>(h0, h1, P0, P0 + 512, y0);

    // layer1: logits from y0/y1 via Q; aggregate y1 rows -> u [1024,4(h'),512]
    attn_kernel<512, 10><<<1024, 128>>>(y0, y1, Q, Q + 2048, u);

    // v[(g,h'), h*128+d] = sum_k u[(g,h'),h,k] W0[k, h*128+d]   (z = h)
    gemm_kernel<<<dim3(2, 64, 4), dim3(16, 16)>>>(u, W0, v, 128, 512, 512, 512, 128, 128, 128);
    // hs0[g, h'*128+d'] = sum u v[g,h',:] W1[:, h'*128+d']      (z = h')
    gemm_kernel<<<dim3(2, 16, 4), dim3(16, 16)>>>(v, W1, hs0, 512, 2048, 512, 512, 512, 128, 128);
    // out = hs0 @ Wfc
    gemm_kernel<<<dim3(4, 16, 1), dim3(16, 16)>>>(hs0, Wfc, out, 512, 512, 256, 256, 0, 0, 0);
}